// round 12
// baseline (speedup 1.0000x reference)
#include <cuda_runtime.h>
#include <cuda_bf16.h>
#include <math.h>
#include <stdint.h>

#define Bq 64
#define TSq 300
#define TDq 180
#define Fq 128
#define Hq 512
#define Lq 4
#define Gq 2048   // 4*H

// ---------------- static device scratch (no runtime allocation) ----------------
__device__ float g_xp[(size_t)2 * Bq * TSq * Gq];
__device__ unsigned g_hwork[2][2 * Bq * Hq];          // packed bf16 hi|lo h state
__device__ float g_cwork[2 * Bq * Hq];
__device__ float g_hs[Lq * Bq * 1024];
__device__ float g_cs[Lq * Bq * 1024];
__device__ float g_h0[Lq * Bq * Hq];
__device__ float g_c0[Lq * Bq * Hq];
__device__ unsigned g_barSlots[16 * 32];              // 16 barrier slots, 128B apart
// packed (bf16hi | bf16lo) operand buffers for tensor-core GEMMs
__device__ unsigned g_Ap[(size_t)Bq * TSq * 1024];    // activations
__device__ unsigned g_Wp[(size_t)2 * Gq * 1024];      // weights

// -------- mma.sync helpers (compute_103-safe) -----
__device__ __forceinline__ uint32_t smem_u32(const void* p) {
    uint32_t a;
    asm("{ .reg .u64 t; cvta.to.shared.u64 t, %1; cvt.u32.u64 %0, t; }" : "=r"(a) : "l"(p));
    return a;
}
#define LDM_X4(r0, r1, r2, r3, addr) \
    asm volatile("ldmatrix.sync.aligned.m8n8.x4.shared.b16 {%0,%1,%2,%3}, [%4];" \
        : "=r"(r0), "=r"(r1), "=r"(r2), "=r"(r3) : "r"(addr))
#define LDM_X2(r0, r1, addr) \
    asm volatile("ldmatrix.sync.aligned.m8n8.x2.shared.b16 {%0,%1}, [%2];" \
        : "=r"(r0), "=r"(r1) : "r"(addr))
#define MMA_BF16(c0, c1, c2, c3, a0, a1, a2, a3, b0, b1) \
    asm volatile("mma.sync.aligned.m16n8k16.row.col.f32.bf16.bf16.f32 " \
        "{%0,%1,%2,%3}, {%4,%5,%6,%7}, {%8,%9}, {%0,%1,%2,%3};" \
        : "+f"(c0), "+f"(c1), "+f"(c2), "+f"(c3) \
        : "r"(a0), "r"(a1), "r"(a2), "r"(a3), "r"(b0), "r"(b1))

__device__ __forceinline__ uint32_t bf2pack(float fhi, float flo) {
    uint32_t r;
    asm("cvt.rn.bf16x2.f32 %0, %1, %2;" : "=r"(r) : "f"(fhi), "f"(flo));
    return r;
}
__device__ __forceinline__ float trunc_hi(float f) {
    return __uint_as_float(__float_as_uint(f) & 0xFFFF0000u);
}
// pack fp32 -> u32: [hi bf16 (trunc) | lo bf16 (RN residual)]
__device__ __forceinline__ unsigned packHL(float f) {
    const float lo = f - trunc_hi(f);
    unsigned lo16;
    asm("{ .reg .b16 t; cvt.rn.bf16.f32 t, %1; cvt.u32.u16 %0, t; }" : "=r"(lo16) : "f"(lo));
    return (__float_as_uint(f) & 0xFFFF0000u) | lo16;
}
__device__ __forceinline__ float unpackHL(unsigned w) {
    return __uint_as_float(w & 0xFFFF0000u) + __uint_as_float(w << 16);
}
__device__ __forceinline__ unsigned prmt(unsigned a, unsigned b, unsigned sel) {
    return __byte_perm(a, b, sel);
}
// fast activations
__device__ __forceinline__ float fast_tanh(float x) {
    float r;
    asm("tanh.approx.f32 %0, %1;" : "=f"(r) : "f"(x));
    return r;
}
__device__ __forceinline__ float fast_sigmoid(float x) {
    return fmaf(0.5f, fast_tanh(0.5f * x), 0.5f);
}

// ---------------------------------------------------------------------------
// grid barrier on a monotonic counter
// ---------------------------------------------------------------------------
__device__ __forceinline__ void gbar(unsigned* slot, unsigned tgt)
{
    __syncthreads();
    if (threadIdx.x == 0) {
        asm volatile("red.release.gpu.global.add.u32 [%0], 1;" :: "l"(slot) : "memory");
        unsigned v;
        while (true) {
            asm volatile("ld.acquire.gpu.global.u32 %0, [%1];" : "=r"(v) : "l"(slot) : "memory");
            if (v >= tgt) break;
            __nanosleep(32);
        }
    }
    __syncthreads();
}

// ---------------------------------------------------------------------------
// fp32 -> packed u32 (bf16 hi|lo), n % 4 == 0
// ---------------------------------------------------------------------------
__global__ void conv_pack(const float* __restrict__ in, unsigned* __restrict__ outp, size_t n)
{
    const size_t i = ((size_t)blockIdx.x * 256 + threadIdx.x) * 4;
    if (i >= n) return;
    const float4 v = *(const float4*)(in + i);
    uint4 o;
    o.x = packHL(v.x); o.y = packHL(v.y); o.z = packHL(v.z); o.w = packHL(v.w);
    *(uint4*)(outp + i) = o;
}

// ---------------------------------------------------------------------------
// Fragment-direct split-bf16 GEMM: C[M,N] = op(A[M,K] @ W[N,K]^T + b)
// D = Ah*Wh + Ah*Wl + Al*Wh. Operands PACKED u32 (bf16hi|bf16lo) per element.
// No smem, no cp.async: mma fragments loaded directly via coalesced LDG.64
// (4 lanes = one full 32B sector) + PRMT to split hi/lo. Reuse via L1.
// CTA 128x128, 256 threads (8 warps 2x4), warp tile 64x32.
// M%128==0, N%128==0, K%16==0.
// ---------------------------------------------------------------------------
__global__ __launch_bounds__(256, 2)
void mma_xp(const unsigned* __restrict__ Ap, const unsigned* __restrict__ Wp,
            const float* __restrict__ bias, float* __restrict__ C,
            int M, int N, int K, size_t wZ, size_t bZ, size_t cZ, int act)
{
    Wp   += blockIdx.z * wZ;
    bias += blockIdx.z * bZ;
    C    += blockIdx.z * cZ;
    const int n0 = blockIdx.x * 128;
    const int m0 = blockIdx.y * 128;

    const int tid  = threadIdx.x;
    const int lane = tid & 31;
    const int warp = tid >> 5;
    const int wm = warp >> 2;          // 0..1 : 64-row block
    const int wn = warp & 3;           // 0..3 : 32-col block

    const int qr = lane >> 2;          // 0..7
    const int qc = (lane & 3) * 2;     // 0,2,4,6

    float acc[4][4][4];
#pragma unroll
    for (int i = 0; i < 4; i++)
#pragma unroll
        for (int j = 0; j < 4; j++)
#pragma unroll
            for (int q = 0; q < 4; q++) acc[i][j][q] = 0.f;

    // base pointers for this thread's fragment rows
    const unsigned* aBase = Ap + (size_t)(m0 + wm * 64 + qr) * K + qc;   // + mt*16*K + k
    const unsigned* wBase = Wp + (size_t)(n0 + wn * 32 + qr) * K + qc;   // + nt*8*K + k

    const int nks = K >> 4;            // k16 steps

    for (int ks = 0; ks < nks; ks++) {
        __syncthreads();               // lockstep warps for L1 tile locality
        const int kb = ks << 4;

        // ---- W fragments: 4 n8-tiles, hi+lo ----
        unsigned bh[4][2], bl[4][2];
#pragma unroll
        for (int nt = 0; nt < 4; nt++) {
            const unsigned* wr = wBase + (size_t)nt * 8 * K + kb;
            const uint2 p = *(const uint2*)wr;        // k, k+1
            const uint2 q = *(const uint2*)(wr + 8);  // k+8, k+9
            bh[nt][0] = prmt(p.x, p.y, 0x7632); bl[nt][0] = prmt(p.x, p.y, 0x5410);
            bh[nt][1] = prmt(q.x, q.y, 0x7632); bl[nt][1] = prmt(q.x, q.y, 0x5410);
        }

        // ---- per m16-tile: A fragments + 12 MMAs ----
#pragma unroll
        for (int mt = 0; mt < 4; mt++) {
            const unsigned* ar0 = aBase + (size_t)mt * 16 * K + kb;
            const unsigned* ar1 = ar0 + (size_t)8 * K;
            const uint2 x0 = *(const uint2*)ar0;        // (r,   k..k+1)
            const uint2 x1 = *(const uint2*)ar1;        // (r+8, k..k+1)
            const uint2 x2 = *(const uint2*)(ar0 + 8);  // (r,   k+8..k+9)
            const uint2 x3 = *(const uint2*)(ar1 + 8);  // (r+8, k+8..k+9)
            unsigned ah[4], al[4];
            ah[0] = prmt(x0.x, x0.y, 0x7632); al[0] = prmt(x0.x, x0.y, 0x5410);
            ah[1] = prmt(x1.x, x1.y, 0x7632); al[1] = prmt(x1.x, x1.y, 0x5410);
            ah[2] = prmt(x2.x, x2.y, 0x7632); al[2] = prmt(x2.x, x2.y, 0x5410);
            ah[3] = prmt(x3.x, x3.y, 0x7632); al[3] = prmt(x3.x, x3.y, 0x5410);
#pragma unroll
            for (int nt = 0; nt < 4; nt++)
                MMA_BF16(acc[mt][nt][0], acc[mt][nt][1], acc[mt][nt][2], acc[mt][nt][3],
                         ah[0], ah[1], ah[2], ah[3], bh[nt][0], bh[nt][1]);
#pragma unroll
            for (int nt = 0; nt < 4; nt++)
                MMA_BF16(acc[mt][nt][0], acc[mt][nt][1], acc[mt][nt][2], acc[mt][nt][3],
                         ah[0], ah[1], ah[2], ah[3], bl[nt][0], bl[nt][1]);
#pragma unroll
            for (int nt = 0; nt < 4; nt++)
                MMA_BF16(acc[mt][nt][0], acc[mt][nt][1], acc[mt][nt][2], acc[mt][nt][3],
                         al[0], al[1], al[2], al[3], bh[nt][0], bh[nt][1]);
        }
    }

    const int mE = m0 + wm * 64 + qr;
    const int nE = n0 + wn * 32 + qc;
#pragma unroll
    for (int mt = 0; mt < 4; mt++) {
#pragma unroll
        for (int nt = 0; nt < 4; nt++) {
            const int m = mE + mt * 16;
            const int n = nE + nt * 8;
            const float b0 = bias[n], b1 = bias[n + 1];
            float v00 = acc[mt][nt][0] + b0, v01 = acc[mt][nt][1] + b1;
            float v10 = acc[mt][nt][2] + b0, v11 = acc[mt][nt][3] + b1;
            if (act) { v00 = tanhf(v00); v01 = tanhf(v01); v10 = tanhf(v10); v11 = tanhf(v11); }
            *(float2*)(C + (size_t)m * N + n)       = make_float2(v00, v01);
            *(float2*)(C + (size_t)(m + 8) * N + n) = make_float2(v10, v11);
        }
    }
}

// ---------------------------------------------------------------------------
// Persistent LSTM layer with tensor-core recurrence (round-9/11 structure;
// y output now ONE packed u32 store into the next GEMM's A buffer).
// ---------------------------------------------------------------------------
template<int NBL>
__global__ __launch_bounds__(256)
void lstm_persist(const float* __restrict__ xp, const float* __restrict__ Whh,
                  const float* __restrict__ h0, const float* __restrict__ c0,
                  unsigned* __restrict__ hA, unsigned* __restrict__ hB,
                  float* __restrict__ cSt,
                  unsigned* __restrict__ yp,
                  float* __restrict__ hFin, float* __restrict__ cFin,
                  int T, int revDir1, int yStride, int yDirMult, int slotIdx)
{
    constexpr int U    = NBL / 4;
    constexpr int USH  = (NBL == 32) ? 3 : 2;
    constexpr int WNT  = NBL / 16;
    constexpr int GSs  = NBL + 2;
    constexpr unsigned G = (NBL == 32) ? 64u : 128u;
    constexpr uint32_t S_AH = 0;
    constexpr uint32_t S_AL = 64 * 1024;
    constexpr uint32_t S_BH = 128 * 1024;
    constexpr uint32_t S_BL = S_BH + NBL * 1024;
    constexpr uint32_t S_GS = S_BL + NBL * 1024;

    extern __shared__ __align__(128) char smem[];
    const uint32_t sb = smem_u32(smem);
    float* Gs = (float*)(smem + S_GS);

    const int tid  = threadIdx.x;
    const int lane = tid & 31;
    const int warp = tid >> 5;
    const int mi = warp >> 1;
    const int nh = warp & 1;

    int dir, u0;
    if (NBL == 32) { dir = blockIdx.x >> 6; u0 = (blockIdx.x & 63) * 8; }
    else           { dir = 0;               u0 = blockIdx.x * 4; }

    unsigned* slot = g_barSlots + (size_t)(slotIdx + ((NBL == 32) ? dir : 0)) * 32;
    unsigned barTgt = 0;

    const float* xpd = xp  + (size_t)dir * Bq * T * Gq;
    const float* Wd  = Whh + (size_t)dir * Gq * Hq;
    unsigned* hArr[2] = { hA + dir * Bq * Hq, hB + dir * Bq * Hq };
    float* cD = cSt + dir * Bq * Hq;

    for (int i = tid; i < NBL * 64; i += 256) {
        const int row = i >> 6;
        const int g   = i & 63;
        const int gate = row / U;
        const int uu   = row & (U - 1);
        const int wrow = (gate << 9) + u0 + uu;
        const float4 va = *(const float4*)(Wd + (size_t)wrow * Hq + g * 8);
        const float4 vb = *(const float4*)(Wd + (size_t)wrow * Hq + g * 8 + 4);
        uint4 hi, lo;
        hi.x = prmt(__float_as_uint(va.x), __float_as_uint(va.y), 0x7632);
        hi.y = prmt(__float_as_uint(va.z), __float_as_uint(va.w), 0x7632);
        hi.z = prmt(__float_as_uint(vb.x), __float_as_uint(vb.y), 0x7632);
        hi.w = prmt(__float_as_uint(vb.z), __float_as_uint(vb.w), 0x7632);
        lo.x = bf2pack(va.y - trunc_hi(va.y), va.x - trunc_hi(va.x));
        lo.y = bf2pack(va.w - trunc_hi(va.w), va.z - trunc_hi(va.z));
        lo.z = bf2pack(vb.y - trunc_hi(vb.y), vb.x - trunc_hi(vb.x));
        lo.w = bf2pack(vb.w - trunc_hi(vb.w), vb.z - trunc_hi(vb.z));
        const uint32_t so = (uint32_t)(row * 1024 + ((g ^ (row & 7)) << 4));
        *(uint4*)(smem + S_BH + so) = hi;
        *(uint4*)(smem + S_BL + so) = lo;
    }

    for (int i = tid; i < Bq * U; i += 256) {
        const int b = i >> USH, uu = i & (U - 1), u = u0 + uu;
        hArr[0][b * Hq + u] = h0 ? packHL(h0[b * Hq + u]) : 0u;
        cD        [b * Hq + u] = c0 ? c0[b * Hq + u] : 0.f;
    }
    barTgt += G; gbar(slot, barTgt);

    const int rowA = (lane & 15);
    const int agoff = lane >> 4;
    const int bnt   = lane >> 4;
    const int bgoff = (lane >> 3) & 1;

    int ping = 0;
    for (int t = 0; t < T; t++) {
        const int tt = (dir == 1 && revDir1) ? (T - 1 - t) : t;
        const unsigned* hI = hArr[ping];
        unsigned*       hO = hArr[ping ^ 1];

#pragma unroll
        for (int it = 0; it < 16; it++) {
            const int slotI = tid + it * 256;
            const int row = slotI >> 6, g = slotI & 63;
            const uint4* p = (const uint4*)(hI + (size_t)row * Hq + g * 8);
            const uint4 v0 = __ldcg(p);
            const uint4 v1 = __ldcg(p + 1);
            uint4 hi, lo;
            hi.x = prmt(v0.x, v0.y, 0x7632); hi.y = prmt(v0.z, v0.w, 0x7632);
            hi.z = prmt(v1.x, v1.y, 0x7632); hi.w = prmt(v1.z, v1.w, 0x7632);
            lo.x = prmt(v0.x, v0.y, 0x5410); lo.y = prmt(v0.z, v0.w, 0x5410);
            lo.z = prmt(v1.x, v1.y, 0x5410); lo.w = prmt(v1.z, v1.w, 0x5410);
            const uint32_t so = (uint32_t)(row * 1024 + ((g ^ (row & 7)) << 4));
            *(uint4*)(smem + S_AH + so) = hi;
            *(uint4*)(smem + S_AL + so) = lo;
        }
        __syncthreads();

        float acc[WNT][4];
#pragma unroll
        for (int nt = 0; nt < WNT; nt++)
#pragma unroll
            for (int q = 0; q < 4; q++) acc[nt][q] = 0.f;

#pragma unroll 4
        for (int ks = 0; ks < 32; ks++) {
            const int rA = mi * 16 + rowA;
            const uint32_t aoff = (uint32_t)(rA * 1024 + (((ks * 2 + agoff) ^ (rA & 7)) << 4));
            uint32_t ah[4], al[4], bh[2 * WNT], bl[2 * WNT];
            LDM_X4(ah[0], ah[1], ah[2], ah[3], sb + S_AH + aoff);
            LDM_X4(al[0], al[1], al[2], al[3], sb + S_AL + aoff);
            if (WNT == 2) {
                const int rB = nh * 16 + bnt * 8 + (lane & 7);
                const uint32_t boff = (uint32_t)(rB * 1024 + (((ks * 2 + bgoff) ^ (rB & 7)) << 4));
                LDM_X4(bh[0], bh[1], bh[2], bh[3], sb + S_BH + boff);
                LDM_X4(bl[0], bl[1], bl[2], bl[3], sb + S_BL + boff);
            } else {
                const int rB = nh * 8 + (lane & 7);
                const uint32_t boff = (uint32_t)(rB * 1024 + (((ks * 2 + bgoff) ^ (rB & 7)) << 4));
                LDM_X2(bh[0], bh[1], sb + S_BH + boff);
                LDM_X2(bl[0], bl[1], sb + S_BL + boff);
            }
#pragma unroll
            for (int nt = 0; nt < WNT; nt++)
                MMA_BF16(acc[nt][0], acc[nt][1], acc[nt][2], acc[nt][3],
                         ah[0], ah[1], ah[2], ah[3], bh[nt * 2], bh[nt * 2 + 1]);
#pragma unroll
            for (int nt = 0; nt < WNT; nt++)
                MMA_BF16(acc[nt][0], acc[nt][1], acc[nt][2], acc[nt][3],
                         ah[0], ah[1], ah[2], ah[3], bl[nt * 2], bl[nt * 2 + 1]);
#pragma unroll
            for (int nt = 0; nt < WNT; nt++)
                MMA_BF16(acc[nt][0], acc[nt][1], acc[nt][2], acc[nt][3],
                         al[0], al[1], al[2], al[3], bh[nt * 2], bh[nt * 2 + 1]);
        }

        {
            const int gr  = lane >> 2;
            const int gcq = (lane & 3) * 2;
            const int m = mi * 16 + gr;
#pragma unroll
            for (int nt = 0; nt < WNT; nt++) {
                const int gc = nh * (WNT * 8) + nt * 8 + gcq;
                *(float2*)&Gs[m * GSs + gc]       = make_float2(acc[nt][0], acc[nt][1]);
                *(float2*)&Gs[(m + 8) * GSs + gc] = make_float2(acc[nt][2], acc[nt][3]);
            }
        }
        __syncthreads();

#pragma unroll
        for (int i = tid; i < Bq * U; i += 256) {
            const int b = i >> USH, uu = i & (U - 1);
            const int u = u0 + uu;
            const size_t xb = ((size_t)b * T + tt) * Gq + u;
            const float iv = Gs[b * GSs + 0 * U + uu] + xpd[xb];
            const float fv = Gs[b * GSs + 1 * U + uu] + xpd[xb + 512];
            const float gv = Gs[b * GSs + 2 * U + uu] + xpd[xb + 1024];
            const float ov = Gs[b * GSs + 3 * U + uu] + xpd[xb + 1536];
            const float cOld = cD[b * Hq + u];
            const float si = fast_sigmoid(iv);
            const float sf = fast_sigmoid(fv);
            const float so = fast_sigmoid(ov);
            const float cN = sf * cOld + si * fast_tanh(gv);
            const float hN = so * fast_tanh(cN);
            const unsigned w = packHL(hN);
            cD[b * Hq + u] = cN;
            hO[b * Hq + u] = w;
            if (yp)
                yp[((size_t)b * T + tt) * yStride + dir * yDirMult + u] = w;
        }

        if (t + 1 < T) { barTgt += G; gbar(slot, barTgt); }
        ping ^= 1;
    }

    if (hFin) {
        for (int i = tid; i < Bq * U; i += 256) {
            const int b = i >> USH, uu = i & (U - 1), u = u0 + uu;
            hFin[b * 1024 + dir * 512 + u] = unpackHL(hArr[ping][b * Hq + u]);
            cFin[b * 1024 + dir * 512 + u] = cD[b * Hq + u];
        }
    }
}

#define SMEM_ENC (128 * 1024 + 2 * 32 * 1024 + 64 * 34 * 4)
#define SMEM_DEC (128 * 1024 + 2 * 16 * 1024 + 64 * 18 * 4)

// decoder input: concat(tgt_in, sc_emb[scenario[b]]) -> packed u32
__global__ void build_dcat(const float* __restrict__ tgt, const float* __restrict__ scEmb,
                           const int* __restrict__ scen, unsigned* __restrict__ op)
{
    const size_t i = (size_t)blockIdx.x * 256 + threadIdx.x;
    if (i >= (size_t)Bq * TDq * 640) return;
    const int r = (int)(i / 640);
    const int j = (int)(i - (size_t)r * 640);
    float v;
    if (j < 128) v = tgt[(size_t)r * 128 + j];
    else         v = scEmb[scen[r / TDq] * 512 + (j - 128)];
    op[i] = packHL(v);
}

// ---------------------------------------------------------------------------
extern "C" void kernel_launch(void* const* d_in, const int* in_sizes, int n_in,
                              void* d_out, int out_size)
{
    (void)in_sizes; (void)n_in; (void)out_size;
    const float* src   = (const float*)d_in[0];
    const float* tgt   = (const float*)d_in[1];
    const int*   scen  = (const int*)  d_in[2];
    const float* eWih0 = (const float*)d_in[3];
    const float* eWhh0 = (const float*)d_in[4];
    const float* eB0   = (const float*)d_in[5];
    const float* eWih  = (const float*)d_in[6];
    const float* eWhh  = (const float*)d_in[7];
    const float* eB    = (const float*)d_in[8];
    const float* hbW   = (const float*)d_in[9];
    const float* hbB   = (const float*)d_in[10];
    const float* cbW   = (const float*)d_in[11];
    const float* cbB   = (const float*)d_in[12];
    const float* scEmb = (const float*)d_in[13];
    const float* dWih0 = (const float*)d_in[14];
    const float* dWhh0 = (const float*)d_in[15];
    const float* dB0   = (const float*)d_in[16];
    const float* dWih  = (const float*)d_in[17];
    const float* dWhh  = (const float*)d_in[18];
    const float* dB    = (const float*)d_in[19];
    const float* outW  = (const float*)d_in[20];
    const float* outB  = (const float*)d_in[21];
    float* out = (float*)d_out;

    float *xp, *cst, *hsP, *csP, *h0P, *c0P;
    unsigned *hwork, *barP, *Ap, *Wp;
    cudaGetSymbolAddress((void**)&xp,    g_xp);
    cudaGetSymbolAddress((void**)&hwork, g_hwork);
    cudaGetSymbolAddress((void**)&cst,   g_cwork);
    cudaGetSymbolAddress((void**)&hsP,   g_hs);
    cudaGetSymbolAddress((void**)&csP,   g_cs);
    cudaGetSymbolAddress((void**)&h0P,   g_h0);
    cudaGetSymbolAddress((void**)&c0P,   g_c0);
    cudaGetSymbolAddress((void**)&barP,  g_barSlots);
    cudaGetSymbolAddress((void**)&Ap,    g_Ap);
    cudaGetSymbolAddress((void**)&Wp,    g_Wp);
    unsigned* hA = hwork;
    unsigned* hB = hwork + 2 * Bq * Hq;

    cudaFuncSetAttribute(lstm_persist<32>, cudaFuncAttributeMaxDynamicSharedMemorySize, SMEM_ENC);
    cudaFuncSetAttribute(lstm_persist<16>, cudaFuncAttributeMaxDynamicSharedMemorySize, SMEM_DEC);

    const int ME = Bq * TSq;   // 19200
    const int MD = Bq * TDq;   // 11520

    // reset barrier counters
    cudaMemsetAsync(barP, 0, 16 * 32 * sizeof(unsigned), 0);

    // ======================= encoder =======================
    conv_pack<<<(int)(((size_t)ME * Fq / 4 + 255) / 256), 256>>>(src, Ap, (size_t)ME * Fq);

    int inDim = Fq;
    for (int l = 0; l < Lq; l++) {
        const float* Wih = l ? eWih + (size_t)(l - 1) * 2 * Gq * 1024 : eWih0;
        const float* bih = l ? eB   + (size_t)(l - 1) * 2 * Gq        : eB0;

        const size_t nW = (size_t)2 * Gq * inDim;
        conv_pack<<<(int)((nW / 4 + 255) / 256), 256>>>(Wih, Wp, nW);
        mma_xp<<<dim3(Gq / 128, ME / 128, 2), 256>>>(
            Ap, Wp, bih, xp, ME, Gq, inDim,
            (size_t)Gq * inDim, (size_t)Gq, (size_t)ME * Gq, 0);

        const float* Whh = l ? eWhh + (size_t)(l - 1) * 2 * Gq * Hq : eWhh0;
        const int lastEnc = (l == Lq - 1);
        lstm_persist<32><<<128, 256, SMEM_ENC>>>(
            xp, Whh, nullptr, nullptr, hA, hB, cst,
            lastEnc ? nullptr : Ap,
            hsP + (size_t)l * Bq * 1024, csP + (size_t)l * Bq * 1024,
            TSq, 1, 1024, 512, 2 * l);

        inDim = 1024;
    }

    // ======================= bridges (tanh, tensor cores) =======================
    conv_pack<<<(int)(((size_t)Lq * Bq * 1024 / 4 + 255) / 256), 256>>>(hsP, Ap, (size_t)Lq * Bq * 1024);
    conv_pack<<<(int)(((size_t)Hq * 1024 / 4 + 255) / 256), 256>>>(hbW, Wp, (size_t)Hq * 1024);
    mma_xp<<<dim3(Hq / 128, (Lq * Bq) / 128, 1), 256>>>(
        Ap, Wp, hbB, h0P, Lq * Bq, Hq, 1024, 0, 0, 0, 1);
    conv_pack<<<(int)(((size_t)Lq * Bq * 1024 / 4 + 255) / 256), 256>>>(csP, Ap, (size_t)Lq * Bq * 1024);
    conv_pack<<<(int)(((size_t)Hq * 1024 / 4 + 255) / 256), 256>>>(cbW, Wp, (size_t)Hq * 1024);
    mma_xp<<<dim3(Hq / 128, (Lq * Bq) / 128, 1), 256>>>(
        Ap, Wp, cbB, c0P, Lq * Bq, Hq, 1024, 0, 0, 0, 1);

    // ======================= decoder =======================
    build_dcat<<<(int)(((size_t)Bq * TDq * 640 + 255) / 256), 256>>>(tgt, scEmb, scen, Ap);

    inDim = Fq + Hq;   // 640
    for (int l = 0; l < Lq; l++) {
        const float* Wih = l ? dWih + (size_t)(l - 1) * Gq * Hq : dWih0;
        const float* bih = l ? dB   + (size_t)(l - 1) * Gq      : dB0;

        const size_t nW = (size_t)Gq * inDim;
        conv_pack<<<(int)((nW / 4 + 255) / 256), 256>>>(Wih, Wp, nW);
        mma_xp<<<dim3(Gq / 128, MD / 128, 1), 256>>>(
            Ap, Wp, bih, xp, MD, Gq, inDim, 0, 0, 0, 0);

        const float* Whh = l ? dWhh + (size_t)(l - 1) * Gq * Hq : dWhh0;
        lstm_persist<16><<<128, 256, SMEM_DEC>>>(
            xp, Whh, h0P + (size_t)l * Bq * Hq, c0P + (size_t)l * Bq * Hq,
            hA, hB, cst, Ap, nullptr, nullptr,
            TDq, 0, 512, 0, 8 + l);

        inDim = Hq;
    }

    // output projection straight into d_out
    conv_pack<<<(int)(((size_t)Fq * Hq / 4 + 255) / 256), 256>>>(outW, Wp, (size_t)Fq * Hq);
    mma_xp<<<dim3(Fq / 128, MD / 128, 1), 256>>>(
        Ap, Wp, outB, out, MD, Fq, Hq, 0, 0, 0, 0);
}

// round 13
// speedup vs baseline: 1.1655x; 1.1655x over previous
#include <cuda_runtime.h>
#include <cuda_bf16.h>
#include <math.h>
#include <stdint.h>

#define Bq 64
#define TSq 300
#define TDq 180
#define Fq 128
#define Hq 512
#define Lq 4
#define Gq 2048   // 4*H

// ---------------- static device scratch (no runtime allocation) ----------------
__device__ float g_xp[(size_t)2 * Bq * TSq * Gq];
__device__ unsigned g_hwork[2][2 * Bq * Hq];          // packed bf16 hi|lo h state
__device__ float g_cwork[2 * Bq * Hq];
__device__ float g_hs[Lq * Bq * 1024];
__device__ float g_cs[Lq * Bq * 1024];
__device__ float g_h0[Lq * Bq * Hq];
__device__ float g_c0[Lq * Bq * Hq];
__device__ unsigned g_barSlots[16 * 32];
// packed (bf16hi | bf16lo) operand buffers for tensor-core GEMMs
__device__ unsigned g_Ap[(size_t)Bq * TSq * 1024];    // activations
__device__ unsigned g_Wp[(size_t)2 * Gq * 1024];      // weights

// -------- helpers (compute_103-safe) -----
__device__ __forceinline__ uint32_t smem_u32(const void* p) {
    uint32_t a;
    asm("{ .reg .u64 t; cvta.to.shared.u64 t, %1; cvt.u32.u64 %0, t; }" : "=r"(a) : "l"(p));
    return a;
}
#define LDM_X4(r0, r1, r2, r3, addr) \
    asm volatile("ldmatrix.sync.aligned.m8n8.x4.shared.b16 {%0,%1,%2,%3}, [%4];" \
        : "=r"(r0), "=r"(r1), "=r"(r2), "=r"(r3) : "r"(addr))
#define LDM_X2(r0, r1, addr) \
    asm volatile("ldmatrix.sync.aligned.m8n8.x2.shared.b16 {%0,%1}, [%2];" \
        : "=r"(r0), "=r"(r1) : "r"(addr))
#define MMA_BF16(c0, c1, c2, c3, a0, a1, a2, a3, b0, b1) \
    asm volatile("mma.sync.aligned.m16n8k16.row.col.f32.bf16.bf16.f32 " \
        "{%0,%1,%2,%3}, {%4,%5,%6,%7}, {%8,%9}, {%0,%1,%2,%3};" \
        : "+f"(c0), "+f"(c1), "+f"(c2), "+f"(c3) \
        : "r"(a0), "r"(a1), "r"(a2), "r"(a3), "r"(b0), "r"(b1))
#define LDS64(v, addr) \
    asm volatile("ld.shared.v2.u32 {%0,%1}, [%2];" : "=r"((v).x), "=r"((v).y) : "r"(addr))

// mbarrier + bulk-async (sm_90 PTX, non-'a')
#define MB_INIT(mb, cnt) \
    asm volatile("mbarrier.init.shared.b64 [%0], %1;" :: "r"(mb), "r"(cnt) : "memory")
#define MB_EXPECT(mb, bytes) \
    asm volatile("mbarrier.arrive.expect_tx.shared.b64 _, [%0], %1;" :: "r"(mb), "r"(bytes) : "memory")
#define MB_WAIT(mb, par) do { \
    uint32_t _mb = (mb), _p = (par), _d; \
    asm volatile("{\n\t.reg .pred p;\n\t" \
        "mbarrier.try_wait.parity.acquire.cta.shared::cta.b64 p, [%1], %2;\n\t" \
        "selp.b32 %0, 1, 0, p;\n\t}" : "=r"(_d) : "r"(_mb), "r"(_p) : "memory"); \
    if (!_d) { \
        asm volatile("{\n\t.reg .pred P1;\n\t" \
            "WL_%=:\n\t" \
            "mbarrier.try_wait.parity.acquire.cta.shared::cta.b64 P1, [%0], %1, 0x989680;\n\t" \
            "@P1 bra.uni WD_%=;\n\t" \
            "bra.uni WL_%=;\n\t" \
            "WD_%=:\n\t}" :: "r"(_mb), "r"(_p) : "memory"); \
    } \
} while (0)
#define BULK_G2S(dst, src, mb) \
    asm volatile("cp.async.bulk.shared::cta.global.mbarrier::complete_tx::bytes [%0], [%1], 128, [%2];" \
        :: "r"(dst), "l"(src), "r"(mb) : "memory")

__device__ __forceinline__ uint32_t bf2pack(float fhi, float flo) {
    uint32_t r;
    asm("cvt.rn.bf16x2.f32 %0, %1, %2;" : "=r"(r) : "f"(fhi), "f"(flo));
    return r;
}
__device__ __forceinline__ float trunc_hi(float f) {
    return __uint_as_float(__float_as_uint(f) & 0xFFFF0000u);
}
__device__ __forceinline__ unsigned packHL(float f) {
    const float lo = f - trunc_hi(f);
    unsigned lo16;
    asm("{ .reg .b16 t; cvt.rn.bf16.f32 t, %1; cvt.u32.u16 %0, t; }" : "=r"(lo16) : "f"(lo));
    return (__float_as_uint(f) & 0xFFFF0000u) | lo16;
}
__device__ __forceinline__ float unpackHL(unsigned w) {
    return __uint_as_float(w & 0xFFFF0000u) + __uint_as_float(w << 16);
}
__device__ __forceinline__ unsigned prmt(unsigned a, unsigned b, unsigned sel) {
    return __byte_perm(a, b, sel);
}
__device__ __forceinline__ float fast_tanh(float x) {
    float r;
    asm("tanh.approx.f32 %0, %1;" : "=f"(r) : "f"(x));
    return r;
}
__device__ __forceinline__ float fast_sigmoid(float x) {
    return fmaf(0.5f, fast_tanh(0.5f * x), 0.5f);
}

// ---------------------------------------------------------------------------
// grid barrier on a monotonic counter
// ---------------------------------------------------------------------------
__device__ __forceinline__ void gbar(unsigned* slot, unsigned tgt)
{
    __syncthreads();
    if (threadIdx.x == 0) {
        asm volatile("red.release.gpu.global.add.u32 [%0], 1;" :: "l"(slot) : "memory");
        unsigned v;
        while (true) {
            asm volatile("ld.acquire.gpu.global.u32 %0, [%1];" : "=r"(v) : "l"(slot) : "memory");
            if (v >= tgt) break;
            __nanosleep(32);
        }
    }
    __syncthreads();
}

// ---------------------------------------------------------------------------
// fp32 -> packed u32 (bf16 hi|lo), n % 4 == 0
// ---------------------------------------------------------------------------
__global__ void conv_pack(const float* __restrict__ in, unsigned* __restrict__ outp, size_t n)
{
    const size_t i = ((size_t)blockIdx.x * 256 + threadIdx.x) * 4;
    if (i >= n) return;
    const float4 v = *(const float4*)(in + i);
    uint4 o;
    o.x = packHL(v.x); o.y = packHL(v.y); o.z = packHL(v.z); o.w = packHL(v.w);
    *(uint4*)(outp + i) = o;
}

// ---------------------------------------------------------------------------
// Bulk-async split-bf16 GEMM: C[M,N] = op(A[M,K] @ W[N,K]^T + b)
// D = Ah*Wh + Ah*Wl + Al*Wh. Packed u32 operands (bf16hi|lo per element).
// cp.async.bulk (128B per op, 256 ops/chunk) fills 160B-padded smem rows;
// fragments via conflict-free LDS.64 + PRMT (round-12 layout, proven correct).
// CTA 128x128, 256 threads (8 warps 2x4), warp 64x32, K chunks of 32,
// 2 stages, 2 CTAs/SM. M%128==0, N%128==0, K%32==0, K>=128.
// ---------------------------------------------------------------------------
#define BK_ROWB   160                      // padded row bytes (32 elems x4 + 32)
#define BK_PLANE  (128 * BK_ROWB)          // 20480
#define BK_STAGE  (2 * BK_PLANE)           // 40960 (A|W)
#define BK_STAGES 2
#define XP_SMEM   (BK_STAGES * BK_STAGE + 64)

__global__ __launch_bounds__(256, 2)
void mma_xp(const unsigned* __restrict__ Ap, const unsigned* __restrict__ Wp,
            const float* __restrict__ bias, float* __restrict__ C,
            int M, int N, int K, size_t wZ, size_t bZ, size_t cZ, int act)
{
    extern __shared__ __align__(128) char smem[];
    const uint32_t sbase  = smem_u32(smem);
    const uint32_t mbBase = sbase + BK_STAGES * BK_STAGE;

    Wp   += blockIdx.z * wZ;
    bias += blockIdx.z * bZ;
    C    += blockIdx.z * cZ;
    const int n0 = blockIdx.x * 128;
    const int m0 = blockIdx.y * 128;

    const int tid  = threadIdx.x;
    const int lane = tid & 31;
    const int warp = tid >> 5;
    const int wm = warp >> 2;          // 0..1
    const int wn = warp & 3;           // 0..3
    const int qr = lane >> 2;          // 0..7
    const int qc = (lane & 3) * 2;     // 0,2,4,6

    // producer mapping: thread t -> plane (0=A,1=W), row 0..127
    const int prow = tid & 127;
    const int ppl  = tid >> 7;
    const unsigned* gsrc = ppl ? (Wp + (size_t)(n0 + prow) * K)
                               : (Ap + (size_t)(m0 + prow) * K);
    const uint32_t sdst0 = sbase + (uint32_t)(ppl * BK_PLANE + prow * BK_ROWB);

    if (tid < BK_STAGES) MB_INIT(mbBase + tid * 8, 1);
    __syncthreads();

    float acc[4][4][4];
#pragma unroll
    for (int i = 0; i < 4; i++)
#pragma unroll
        for (int j = 0; j < 4; j++)
#pragma unroll
            for (int q = 0; q < 4; q++) acc[i][j][q] = 0.f;

    const int nch = K >> 5;

#define BISSUE(c) do { \
    const int _s = (c) & 1; \
    const uint32_t _mb = mbBase + _s * 8; \
    if (tid == 0) MB_EXPECT(_mb, 32768); \
    BULK_G2S(sdst0 + (uint32_t)_s * BK_STAGE, gsrc + ((size_t)(c) << 5), _mb); \
} while (0)

    BISSUE(0);
    BISSUE(1);

    for (int c = 0; c < nch; c++) {
        MB_WAIT(mbBase + (c & 1) * 8, (c >> 1) & 1);

        const uint32_t bufA = sbase + (uint32_t)(c & 1) * BK_STAGE;
        const uint32_t bufW = bufA + BK_PLANE;

#pragma unroll
        for (int ks = 0; ks < 2; ks++) {
            const int eb = ks * 16 + qc;                   // elem base in chunk
            // W fragments: 4 n8-tiles
            unsigned bh[4][2], bl[4][2];
#pragma unroll
            for (int nt = 0; nt < 4; nt++) {
                const int rw = wn * 32 + nt * 8 + qr;
                const uint32_t wa = bufW + (uint32_t)(rw * BK_ROWB + eb * 4);
                uint2 p, q;
                LDS64(p, wa);
                LDS64(q, wa + 32);
                bh[nt][0] = prmt(p.x, p.y, 0x7632); bl[nt][0] = prmt(p.x, p.y, 0x5410);
                bh[nt][1] = prmt(q.x, q.y, 0x7632); bl[nt][1] = prmt(q.x, q.y, 0x5410);
            }
            // per m16-tile: A fragments + 12 MMAs
#pragma unroll
            for (int mt = 0; mt < 4; mt++) {
                const int r0 = wm * 64 + mt * 16 + qr;
                const uint32_t a0 = bufA + (uint32_t)(r0 * BK_ROWB + eb * 4);
                const uint32_t a1 = a0 + 8 * BK_ROWB;
                uint2 x0, x1, x2, x3;
                LDS64(x0, a0);
                LDS64(x1, a1);
                LDS64(x2, a0 + 32);
                LDS64(x3, a1 + 32);
                unsigned ah[4], al[4];
                ah[0] = prmt(x0.x, x0.y, 0x7632); al[0] = prmt(x0.x, x0.y, 0x5410);
                ah[1] = prmt(x1.x, x1.y, 0x7632); al[1] = prmt(x1.x, x1.y, 0x5410);
                ah[2] = prmt(x2.x, x2.y, 0x7632); al[2] = prmt(x2.x, x2.y, 0x5410);
                ah[3] = prmt(x3.x, x3.y, 0x7632); al[3] = prmt(x3.x, x3.y, 0x5410);
#pragma unroll
                for (int nt = 0; nt < 4; nt++)
                    MMA_BF16(acc[mt][nt][0], acc[mt][nt][1], acc[mt][nt][2], acc[mt][nt][3],
                             ah[0], ah[1], ah[2], ah[3], bh[nt][0], bh[nt][1]);
#pragma unroll
                for (int nt = 0; nt < 4; nt++)
                    MMA_BF16(acc[mt][nt][0], acc[mt][nt][1], acc[mt][nt][2], acc[mt][nt][3],
                             ah[0], ah[1], ah[2], ah[3], bl[nt][0], bl[nt][1]);
#pragma unroll
                for (int nt = 0; nt < 4; nt++)
                    MMA_BF16(acc[mt][nt][0], acc[mt][nt][1], acc[mt][nt][2], acc[mt][nt][3],
                             al[0], al[1], al[2], al[3], bh[nt][0], bh[nt][1]);
            }
        }

        __syncthreads();                    // all reads of this stage done
        if (c + 2 < nch) BISSUE(c + 2);     // refill the stage just consumed
    }

    const int mE = m0 + wm * 64 + qr;
    const int nE = n0 + wn * 32 + qc;
#pragma unroll
    for (int mt = 0; mt < 4; mt++) {
#pragma unroll
        for (int nt = 0; nt < 4; nt++) {
            const int m = mE + mt * 16;
            const int n = nE + nt * 8;
            const float b0 = bias[n], b1 = bias[n + 1];
            float v00 = acc[mt][nt][0] + b0, v01 = acc[mt][nt][1] + b1;
            float v10 = acc[mt][nt][2] + b0, v11 = acc[mt][nt][3] + b1;
            if (act) { v00 = tanhf(v00); v01 = tanhf(v01); v10 = tanhf(v10); v11 = tanhf(v11); }
            *(float2*)(C + (size_t)m * N + n)       = make_float2(v00, v01);
            *(float2*)(C + (size_t)(m + 8) * N + n) = make_float2(v10, v11);
        }
    }
}

// ---------------------------------------------------------------------------
// Persistent LSTM layer with tensor-core recurrence (round-12, best measured).
// ---------------------------------------------------------------------------
template<int NBL>
__global__ __launch_bounds__(256)
void lstm_persist(const float* __restrict__ xp, const float* __restrict__ Whh,
                  const float* __restrict__ h0, const float* __restrict__ c0,
                  unsigned* __restrict__ hA, unsigned* __restrict__ hB,
                  float* __restrict__ cSt,
                  unsigned* __restrict__ yp,
                  float* __restrict__ hFin, float* __restrict__ cFin,
                  int T, int revDir1, int yStride, int yDirMult, int slotIdx)
{
    constexpr int U    = NBL / 4;
    constexpr int USH  = (NBL == 32) ? 3 : 2;
    constexpr int WNT  = NBL / 16;
    constexpr int GSs  = NBL + 2;
    constexpr unsigned G = (NBL == 32) ? 64u : 128u;
    constexpr uint32_t S_AH = 0;
    constexpr uint32_t S_AL = 64 * 1024;
    constexpr uint32_t S_BH = 128 * 1024;
    constexpr uint32_t S_BL = S_BH + NBL * 1024;
    constexpr uint32_t S_GS = S_BL + NBL * 1024;

    extern __shared__ __align__(128) char smem[];
    const uint32_t sb = smem_u32(smem);
    float* Gs = (float*)(smem + S_GS);

    const int tid  = threadIdx.x;
    const int lane = tid & 31;
    const int warp = tid >> 5;
    const int mi = warp >> 1;
    const int nh = warp & 1;

    int dir, u0;
    if (NBL == 32) { dir = blockIdx.x >> 6; u0 = (blockIdx.x & 63) * 8; }
    else           { dir = 0;               u0 = blockIdx.x * 4; }

    unsigned* slot = g_barSlots + (size_t)(slotIdx + ((NBL == 32) ? dir : 0)) * 32;
    unsigned barTgt = 0;

    const float* xpd = xp  + (size_t)dir * Bq * T * Gq;
    const float* Wd  = Whh + (size_t)dir * Gq * Hq;
    unsigned* hArr[2] = { hA + dir * Bq * Hq, hB + dir * Bq * Hq };
    float* cD = cSt + dir * Bq * Hq;

    for (int i = tid; i < NBL * 64; i += 256) {
        const int row = i >> 6;
        const int g   = i & 63;
        const int gate = row / U;
        const int uu   = row & (U - 1);
        const int wrow = (gate << 9) + u0 + uu;
        const float4 va = *(const float4*)(Wd + (size_t)wrow * Hq + g * 8);
        const float4 vb = *(const float4*)(Wd + (size_t)wrow * Hq + g * 8 + 4);
        uint4 hi, lo;
        hi.x = prmt(__float_as_uint(va.x), __float_as_uint(va.y), 0x7632);
        hi.y = prmt(__float_as_uint(va.z), __float_as_uint(va.w), 0x7632);
        hi.z = prmt(__float_as_uint(vb.x), __float_as_uint(vb.y), 0x7632);
        hi.w = prmt(__float_as_uint(vb.z), __float_as_uint(vb.w), 0x7632);
        lo.x = bf2pack(va.y - trunc_hi(va.y), va.x - trunc_hi(va.x));
        lo.y = bf2pack(va.w - trunc_hi(va.w), va.z - trunc_hi(va.z));
        lo.z = bf2pack(vb.y - trunc_hi(vb.y), vb.x - trunc_hi(vb.x));
        lo.w = bf2pack(vb.w - trunc_hi(vb.w), vb.z - trunc_hi(vb.z));
        const uint32_t so = (uint32_t)(row * 1024 + ((g ^ (row & 7)) << 4));
        *(uint4*)(smem + S_BH + so) = hi;
        *(uint4*)(smem + S_BL + so) = lo;
    }

    for (int i = tid; i < Bq * U; i += 256) {
        const int b = i >> USH, uu = i & (U - 1), u = u0 + uu;
        hArr[0][b * Hq + u] = h0 ? packHL(h0[b * Hq + u]) : 0u;
        cD        [b * Hq + u] = c0 ? c0[b * Hq + u] : 0.f;
    }
    barTgt += G; gbar(slot, barTgt);

    const int rowA = (lane & 15);
    const int agoff = lane >> 4;
    const int bnt   = lane >> 4;
    const int bgoff = (lane >> 3) & 1;

    int ping = 0;
    for (int t = 0; t < T; t++) {
        const int tt = (dir == 1 && revDir1) ? (T - 1 - t) : t;
        const unsigned* hI = hArr[ping];
        unsigned*       hO = hArr[ping ^ 1];

#pragma unroll
        for (int it = 0; it < 16; it++) {
            const int slotI = tid + it * 256;
            const int row = slotI >> 6, g = slotI & 63;
            const uint4* p = (const uint4*)(hI + (size_t)row * Hq + g * 8);
            const uint4 v0 = __ldcg(p);
            const uint4 v1 = __ldcg(p + 1);
            uint4 hi, lo;
            hi.x = prmt(v0.x, v0.y, 0x7632); hi.y = prmt(v0.z, v0.w, 0x7632);
            hi.z = prmt(v1.x, v1.y, 0x7632); hi.w = prmt(v1.z, v1.w, 0x7632);
            lo.x = prmt(v0.x, v0.y, 0x5410); lo.y = prmt(v0.z, v0.w, 0x5410);
            lo.z = prmt(v1.x, v1.y, 0x5410); lo.w = prmt(v1.z, v1.w, 0x5410);
            const uint32_t so = (uint32_t)(row * 1024 + ((g ^ (row & 7)) << 4));
            *(uint4*)(smem + S_AH + so) = hi;
            *(uint4*)(smem + S_AL + so) = lo;
        }
        __syncthreads();

        float acc[WNT][4];
#pragma unroll
        for (int nt = 0; nt < WNT; nt++)
#pragma unroll
            for (int q = 0; q < 4; q++) acc[nt][q] = 0.f;

#pragma unroll 4
        for (int ks = 0; ks < 32; ks++) {
            const int rA = mi * 16 + rowA;
            const uint32_t aoff = (uint32_t)(rA * 1024 + (((ks * 2 + agoff) ^ (rA & 7)) << 4));
            uint32_t ah[4], al[4], bh[2 * WNT], bl[2 * WNT];
            LDM_X4(ah[0], ah[1], ah[2], ah[3], sb + S_AH + aoff);
            LDM_X4(al[0], al[1], al[2], al[3], sb + S_AL + aoff);
            if (WNT == 2) {
                const int rB = nh * 16 + bnt * 8 + (lane & 7);
                const uint32_t boff = (uint32_t)(rB * 1024 + (((ks * 2 + bgoff) ^ (rB & 7)) << 4));
                LDM_X4(bh[0], bh[1], bh[2], bh[3], sb + S_BH + boff);
                LDM_X4(bl[0], bl[1], bl[2], bl[3], sb + S_BL + boff);
            } else {
                const int rB = nh * 8 + (lane & 7);
                const uint32_t boff = (uint32_t)(rB * 1024 + (((ks * 2 + bgoff) ^ (rB & 7)) << 4));
                LDM_X2(bh[0], bh[1], sb + S_BH + boff);
                LDM_X2(bl[0], bl[1], sb + S_BL + boff);
            }
#pragma unroll
            for (int nt = 0; nt < WNT; nt++)
                MMA_BF16(acc[nt][0], acc[nt][1], acc[nt][2], acc[nt][3],
                         ah[0], ah[1], ah[2], ah[3], bh[nt * 2], bh[nt * 2 + 1]);
#pragma unroll
            for (int nt = 0; nt < WNT; nt++)
                MMA_BF16(acc[nt][0], acc[nt][1], acc[nt][2], acc[nt][3],
                         ah[0], ah[1], ah[2], ah[3], bl[nt * 2], bl[nt * 2 + 1]);
#pragma unroll
            for (int nt = 0; nt < WNT; nt++)
                MMA_BF16(acc[nt][0], acc[nt][1], acc[nt][2], acc[nt][3],
                         al[0], al[1], al[2], al[3], bh[nt * 2], bh[nt * 2 + 1]);
        }

        {
            const int gr  = lane >> 2;
            const int gcq = (lane & 3) * 2;
            const int m = mi * 16 + gr;
#pragma unroll
            for (int nt = 0; nt < WNT; nt++) {
                const int gc = nh * (WNT * 8) + nt * 8 + gcq;
                *(float2*)&Gs[m * GSs + gc]       = make_float2(acc[nt][0], acc[nt][1]);
                *(float2*)&Gs[(m + 8) * GSs + gc] = make_float2(acc[nt][2], acc[nt][3]);
            }
        }
        __syncthreads();

#pragma unroll
        for (int i = tid; i < Bq * U; i += 256) {
            const int b = i >> USH, uu = i & (U - 1);
            const int u = u0 + uu;
            const size_t xb = ((size_t)b * T + tt) * Gq + u;
            const float iv = Gs[b * GSs + 0 * U + uu] + xpd[xb];
            const float fv = Gs[b * GSs + 1 * U + uu] + xpd[xb + 512];
            const float gv = Gs[b * GSs + 2 * U + uu] + xpd[xb + 1024];
            const float ov = Gs[b * GSs + 3 * U + uu] + xpd[xb + 1536];
            const float cOld = cD[b * Hq + u];
            const float si = fast_sigmoid(iv);
            const float sf = fast_sigmoid(fv);
            const float so = fast_sigmoid(ov);
            const float cN = sf * cOld + si * fast_tanh(gv);
            const float hN = so * fast_tanh(cN);
            const unsigned w = packHL(hN);
            cD[b * Hq + u] = cN;
            hO[b * Hq + u] = w;
            if (yp)
                yp[((size_t)b * T + tt) * yStride + dir * yDirMult + u] = w;
        }

        if (t + 1 < T) { barTgt += G; gbar(slot, barTgt); }
        ping ^= 1;
    }

    if (hFin) {
        for (int i = tid; i < Bq * U; i += 256) {
            const int b = i >> USH, uu = i & (U - 1), u = u0 + uu;
            hFin[b * 1024 + dir * 512 + u] = unpackHL(hArr[ping][b * Hq + u]);
            cFin[b * 1024 + dir * 512 + u] = cD[b * Hq + u];
        }
    }
}

#define SMEM_ENC (128 * 1024 + 2 * 32 * 1024 + 64 * 34 * 4)
#define SMEM_DEC (128 * 1024 + 2 * 16 * 1024 + 64 * 18 * 4)

// decoder input: concat(tgt_in, sc_emb[scenario[b]]) -> packed u32
__global__ void build_dcat(const float* __restrict__ tgt, const float* __restrict__ scEmb,
                           const int* __restrict__ scen, unsigned* __restrict__ op)
{
    const size_t i = (size_t)blockIdx.x * 256 + threadIdx.x;
    if (i >= (size_t)Bq * TDq * 640) return;
    const int r = (int)(i / 640);
    const int j = (int)(i - (size_t)r * 640);
    float v;
    if (j < 128) v = tgt[(size_t)r * 128 + j];
    else         v = scEmb[scen[r / TDq] * 512 + (j - 128)];
    op[i] = packHL(v);
}

// ---------------------------------------------------------------------------
extern "C" void kernel_launch(void* const* d_in, const int* in_sizes, int n_in,
                              void* d_out, int out_size)
{
    (void)in_sizes; (void)n_in; (void)out_size;
    const float* src   = (const float*)d_in[0];
    const float* tgt   = (const float*)d_in[1];
    const int*   scen  = (const int*)  d_in[2];
    const float* eWih0 = (const float*)d_in[3];
    const float* eWhh0 = (const float*)d_in[4];
    const float* eB0   = (const float*)d_in[5];
    const float* eWih  = (const float*)d_in[6];
    const float* eWhh  = (const float*)d_in[7];
    const float* eB    = (const float*)d_in[8];
    const float* hbW   = (const float*)d_in[9];
    const float* hbB   = (const float*)d_in[10];
    const float* cbW   = (const float*)d_in[11];
    const float* cbB   = (const float*)d_in[12];
    const float* scEmb = (const float*)d_in[13];
    const float* dWih0 = (const float*)d_in[14];
    const float* dWhh0 = (const float*)d_in[15];
    const float* dB0   = (const float*)d_in[16];
    const float* dWih  = (const float*)d_in[17];
    const float* dWhh  = (const float*)d_in[18];
    const float* dB    = (const float*)d_in[19];
    const float* outW  = (const float*)d_in[20];
    const float* outB  = (const float*)d_in[21];
    float* out = (float*)d_out;

    float *xp, *cst, *hsP, *csP, *h0P, *c0P;
    unsigned *hwork, *barP, *Ap, *Wp;
    cudaGetSymbolAddress((void**)&xp,    g_xp);
    cudaGetSymbolAddress((void**)&hwork, g_hwork);
    cudaGetSymbolAddress((void**)&cst,   g_cwork);
    cudaGetSymbolAddress((void**)&hsP,   g_hs);
    cudaGetSymbolAddress((void**)&csP,   g_cs);
    cudaGetSymbolAddress((void**)&h0P,   g_h0);
    cudaGetSymbolAddress((void**)&c0P,   g_c0);
    cudaGetSymbolAddress((void**)&barP,  g_barSlots);
    cudaGetSymbolAddress((void**)&Ap,    g_Ap);
    cudaGetSymbolAddress((void**)&Wp,    g_Wp);
    unsigned* hA = hwork;
    unsigned* hB = hwork + 2 * Bq * Hq;

    cudaFuncSetAttribute(lstm_persist<32>, cudaFuncAttributeMaxDynamicSharedMemorySize, SMEM_ENC);
    cudaFuncSetAttribute(lstm_persist<16>, cudaFuncAttributeMaxDynamicSharedMemorySize, SMEM_DEC);
    cudaFuncSetAttribute(mma_xp, cudaFuncAttributeMaxDynamicSharedMemorySize, XP_SMEM);

    const int ME = Bq * TSq;   // 19200
    const int MD = Bq * TDq;   // 11520

    // reset barrier counters
    cudaMemsetAsync(barP, 0, 16 * 32 * sizeof(unsigned), 0);

    // ======================= encoder =======================
    conv_pack<<<(int)(((size_t)ME * Fq / 4 + 255) / 256), 256>>>(src, Ap, (size_t)ME * Fq);

    int inDim = Fq;
    for (int l = 0; l < Lq; l++) {
        const float* Wih = l ? eWih + (size_t)(l - 1) * 2 * Gq * 1024 : eWih0;
        const float* bih = l ? eB   + (size_t)(l - 1) * 2 * Gq        : eB0;

        const size_t nW = (size_t)2 * Gq * inDim;
        conv_pack<<<(int)((nW / 4 + 255) / 256), 256>>>(Wih, Wp, nW);
        mma_xp<<<dim3(Gq / 128, ME / 128, 2), 256, XP_SMEM>>>(
            Ap, Wp, bih, xp, ME, Gq, inDim,
            (size_t)Gq * inDim, (size_t)Gq, (size_t)ME * Gq, 0);

        const float* Whh = l ? eWhh + (size_t)(l - 1) * 2 * Gq * Hq : eWhh0;
        const int lastEnc = (l == Lq - 1);
        lstm_persist<32><<<128, 256, SMEM_ENC>>>(
            xp, Whh, nullptr, nullptr, hA, hB, cst,
            lastEnc ? nullptr : Ap,
            hsP + (size_t)l * Bq * 1024, csP + (size_t)l * Bq * 1024,
            TSq, 1, 1024, 512, 2 * l);

        inDim = 1024;
    }

    // ======================= bridges (tanh, tensor cores) =======================
    conv_pack<<<(int)(((size_t)Lq * Bq * 1024 / 4 + 255) / 256), 256>>>(hsP, Ap, (size_t)Lq * Bq * 1024);
    conv_pack<<<(int)(((size_t)Hq * 1024 / 4 + 255) / 256), 256>>>(hbW, Wp, (size_t)Hq * 1024);
    mma_xp<<<dim3(Hq / 128, (Lq * Bq) / 128, 1), 256, XP_SMEM>>>(
        Ap, Wp, hbB, h0P, Lq * Bq, Hq, 1024, 0, 0, 0, 1);
    conv_pack<<<(int)(((size_t)Lq * Bq * 1024 / 4 + 255) / 256), 256>>>(csP, Ap, (size_t)Lq * Bq * 1024);
    conv_pack<<<(int)(((size_t)Hq * 1024 / 4 + 255) / 256), 256>>>(cbW, Wp, (size_t)Hq * 1024);
    mma_xp<<<dim3(Hq / 128, (Lq * Bq) / 128, 1), 256, XP_SMEM>>>(
        Ap, Wp, cbB, c0P, Lq * Bq, Hq, 1024, 0, 0, 0, 1);

    // ======================= decoder =======================
    build_dcat<<<(int)(((size_t)Bq * TDq * 640 + 255) / 256), 256>>>(tgt, scEmb, scen, Ap);

    inDim = Fq + Hq;   // 640
    for (int l = 0; l < Lq; l++) {
        const float* Wih = l ? dWih + (size_t)(l - 1) * Gq * Hq : dWih0;
        const float* bih = l ? dB   + (size_t)(l - 1) * Gq      : dB0;

        const size_t nW = (size_t)Gq * inDim;
        conv_pack<<<(int)((nW / 4 + 255) / 256), 256>>>(Wih, Wp, nW);
        mma_xp<<<dim3(Gq / 128, MD / 128, 1), 256, XP_SMEM>>>(
            Ap, Wp, bih, xp, MD, Gq, inDim, 0, 0, 0, 0);

        const float* Whh = l ? dWhh + (size_t)(l - 1) * Gq * Hq : dWhh0;
        lstm_persist<16><<<128, 256, SMEM_DEC>>>(
            xp, Whh, h0P + (size_t)l * Bq * Hq, c0P + (size_t)l * Bq * Hq,
            hA, hB, cst, Ap, nullptr, nullptr,
            TDq, 0, 512, 0, 8 + l);

        inDim = Hq;
    }

    // output projection straight into d_out
    conv_pack<<<(int)(((size_t)Fq * Hq / 4 + 255) / 256), 256>>>(outW, Wp, (size_t)Fq * Hq);
    mma_xp<<<dim3(Fq / 128, MD / 128, 1), 256, XP_SMEM>>>(
        Ap, Wp, outB, out, MD, Fq, Hq, 0, 0, 0, 0);
}